// round 2
// baseline (speedup 1.0000x reference)
#include <cuda_runtime.h>
#include <math.h>

#define B_SZ    2
#define S_LEN   2048
#define D_MOD   1024
#define H_NUM   16
#define DK      64
#define ROWS    (B_SZ * S_LEN)           // 4096

// ---------------- scratch (static device arrays; no allocations) ----------
__device__ float g_Q  [B_SZ * H_NUM * S_LEN * DK];   // [B,H,S,DK]
__device__ float g_K  [B_SZ * H_NUM * S_LEN * DK];
__device__ float g_V  [B_SZ * H_NUM * S_LEN * DK];
__device__ float g_ctx[ROWS * D_MOD];                // merged heads, row-major
__device__ float g_prj[ROWS * D_MOD];                // context @ Wo + bo

// ---------------- SGEMM: C = A[ROWS,1024] @ W[1024,1024] + bias -----------
// 128x128 block tile, BK=8, 256 threads, 8x8 per-thread microtile.
// HEADS_OUT=true  -> scatter to [B,H,S,DK] layout (QKV path)
// HEADS_OUT=false -> plain row-major [ROWS, D_MOD]
#define BM 128
#define BN 128
#define BKK 8
#define TM 8
#define TN 8

template <bool HEADS_OUT>
__global__ __launch_bounds__(256) void sgemm_bias(
    const float* __restrict__ A,
    const float* __restrict__ W,
    const float* __restrict__ bias,
    float* __restrict__ C)
{
    __shared__ float As[BKK][BM];
    __shared__ float Bs[BKK][BN];

    const int tid = threadIdx.x;
    const int m0 = blockIdx.y * BM;
    const int n0 = blockIdx.x * BN;

    // A tile loader: 128 rows x 8 cols = 256 float4, one per thread
    const int a_row = tid >> 1;
    const int a_col = (tid & 1) << 2;
    // B tile loader: 8 rows x 128 cols = 256 float4
    const int b_row = tid >> 5;
    const int b_col = (tid & 31) << 2;

    const int tx = tid & 15;   // col group
    const int ty = tid >> 4;   // row group

    float acc[TM][TN];
#pragma unroll
    for (int i = 0; i < TM; i++)
#pragma unroll
        for (int j = 0; j < TN; j++) acc[i][j] = 0.f;

    for (int k0 = 0; k0 < D_MOD; k0 += BKK) {
        float4 av = *(const float4*)(A + (size_t)(m0 + a_row) * D_MOD + k0 + a_col);
        As[a_col + 0][a_row] = av.x;
        As[a_col + 1][a_row] = av.y;
        As[a_col + 2][a_row] = av.z;
        As[a_col + 3][a_row] = av.w;
        *(float4*)&Bs[b_row][b_col] =
            *(const float4*)(W + (size_t)(k0 + b_row) * D_MOD + n0 + b_col);
        __syncthreads();

#pragma unroll
        for (int k = 0; k < BKK; k++) {
            float ar[TM], br[TN];
#pragma unroll
            for (int i = 0; i < 2; i++) {
                float4 t = *(const float4*)&As[k][ty * TM + i * 4];
                ar[i * 4 + 0] = t.x; ar[i * 4 + 1] = t.y;
                ar[i * 4 + 2] = t.z; ar[i * 4 + 3] = t.w;
            }
#pragma unroll
            for (int j = 0; j < 2; j++) {
                float4 t = *(const float4*)&Bs[k][tx * TN + j * 4];
                br[j * 4 + 0] = t.x; br[j * 4 + 1] = t.y;
                br[j * 4 + 2] = t.z; br[j * 4 + 3] = t.w;
            }
#pragma unroll
            for (int i = 0; i < TM; i++)
#pragma unroll
                for (int j = 0; j < TN; j++)
                    acc[i][j] = fmaf(ar[i], br[j], acc[i][j]);
        }
        __syncthreads();
    }

    // epilogue
#pragma unroll
    for (int i = 0; i < TM; i++) {
        const int m = m0 + ty * TM + i;
#pragma unroll
        for (int j = 0; j < TN; j++) {
            const int n = n0 + tx * TN + j;
            const float v = acc[i][j] + bias[n];
            if (HEADS_OUT) {
                const int b = m >> 11;          // m / 2048
                const int s = m & (S_LEN - 1);
                const int h = n >> 6;           // n / 64
                const int d = n & 63;
                C[(((size_t)(b * H_NUM + h)) * S_LEN + s) * DK + d] = v;
            } else {
                C[(size_t)m * D_MOD + n] = v;
            }
        }
    }
}

// ---------------- flash attention (fp32, online softmax) ------------------
// 1 thread = 1 query row; 128 queries per block; KV tiles of 32x64 in smem.
__global__ __launch_bounds__(128) void attn_kernel(
    const float* __restrict__ Q,
    const float* __restrict__ K,
    const float* __restrict__ V,
    float* __restrict__ Ctx)
{
    const int bh = blockIdx.y;               // 0..31 (b*16+h)
    const int q0 = blockIdx.x * 128;
    const int tid = threadIdx.x;

    const float* Qb = Q + (size_t)bh * S_LEN * DK;
    const float* Kb = K + (size_t)bh * S_LEN * DK;
    const float* Vb = V + (size_t)bh * S_LEN * DK;

    __shared__ float Ks[32][DK];
    __shared__ float Vs[32][DK];

    float4 q[16];
    const float4* qr = (const float4*)(Qb + (size_t)(q0 + tid) * DK);
#pragma unroll
    for (int i = 0; i < 16; i++) q[i] = qr[i];

    float4 acc[16];
#pragma unroll
    for (int i = 0; i < 16; i++) acc[i] = make_float4(0.f, 0.f, 0.f, 0.f);
    float m = -1e30f, l = 0.f;
    const float scale = 0.125f;              // 1/sqrt(64)

    for (int kt = 0; kt < S_LEN; kt += 32) {
        __syncthreads();
#pragma unroll
        for (int i = 0; i < 4; i++) {
            const int idx = tid + i * 128;   // 0..511
            const int r = idx >> 4;
            const int c = (idx & 15) << 2;
            *(float4*)&Ks[r][c] = *(const float4*)(Kb + (size_t)(kt + r) * DK + c);
            *(float4*)&Vs[r][c] = *(const float4*)(Vb + (size_t)(kt + r) * DK + c);
        }
        __syncthreads();

        float s[32];
#pragma unroll
        for (int j = 0; j < 32; j++) {
            const float4* kr = (const float4*)Ks[j];
            float sum = 0.f;
#pragma unroll
            for (int i = 0; i < 16; i++) {
                float4 kv = kr[i];
                sum = fmaf(q[i].x, kv.x, sum);
                sum = fmaf(q[i].y, kv.y, sum);
                sum = fmaf(q[i].z, kv.z, sum);
                sum = fmaf(q[i].w, kv.w, sum);
            }
            s[j] = sum * scale;
        }

        float tmax = s[0];
#pragma unroll
        for (int j = 1; j < 32; j++) tmax = fmaxf(tmax, s[j]);
        const float mn = fmaxf(m, tmax);
        const float f = __expf(m - mn);
        m = mn;
        l *= f;
#pragma unroll
        for (int i = 0; i < 16; i++) {
            acc[i].x *= f; acc[i].y *= f; acc[i].z *= f; acc[i].w *= f;
        }
#pragma unroll
        for (int j = 0; j < 32; j++) {
            const float p = __expf(s[j] - m);
            l += p;
            const float4* vr = (const float4*)Vs[j];
#pragma unroll
            for (int i = 0; i < 16; i++) {
                float4 vv = vr[i];
                acc[i].x = fmaf(p, vv.x, acc[i].x);
                acc[i].y = fmaf(p, vv.y, acc[i].y);
                acc[i].z = fmaf(p, vv.z, acc[i].z);
                acc[i].w = fmaf(p, vv.w, acc[i].w);
            }
        }
    }

    const float inv = 1.f / l;
    const int b = bh >> 4, h = bh & 15;
    float* out = Ctx + (size_t)(b * S_LEN + q0 + tid) * D_MOD + h * DK;
#pragma unroll
    for (int i = 0; i < 16; i++) {
        float4 o = acc[i];
        o.x *= inv; o.y *= inv; o.z *= inv; o.w *= inv;
        ((float4*)out)[i] = o;
    }
}

// ---------------- residual + LayerNorm ------------------------------------
__global__ __launch_bounds__(256) void ln_kernel(
    const float* __restrict__ x,
    const float* __restrict__ prj,
    const float* __restrict__ gamma,
    const float* __restrict__ beta,
    float* __restrict__ out)
{
    const int row = blockIdx.x;
    const int tid = threadIdx.x;

    const float4 xv = ((const float4*)(x   + (size_t)row * D_MOD))[tid];
    const float4 pv = ((const float4*)(prj + (size_t)row * D_MOD))[tid];
    float4 h;
    h.x = xv.x + pv.x; h.y = xv.y + pv.y; h.z = xv.z + pv.z; h.w = xv.w + pv.w;

    float sum = h.x + h.y + h.z + h.w;
    float ssq = h.x * h.x + h.y * h.y + h.z * h.z + h.w * h.w;
#pragma unroll
    for (int o = 16; o > 0; o >>= 1) {
        sum += __shfl_xor_sync(0xffffffffu, sum, o);
        ssq += __shfl_xor_sync(0xffffffffu, ssq, o);
    }
    __shared__ float rs[8], rq[8];
    const int warp = tid >> 5, lane = tid & 31;
    if (lane == 0) { rs[warp] = sum; rq[warp] = ssq; }
    __syncthreads();
    float ts = 0.f, tq = 0.f;
#pragma unroll
    for (int i = 0; i < 8; i++) { ts += rs[i]; tq += rq[i]; }

    const float mu   = ts * (1.f / (float)D_MOD);
    const float var  = tq * (1.f / (float)D_MOD) - mu * mu;
    const float rstd = rsqrtf(var + 1e-5f);

    const float4 g  = ((const float4*)gamma)[tid];
    const float4 be = ((const float4*)beta)[tid];
    float4 o;
    o.x = (h.x - mu) * rstd * g.x + be.x;
    o.y = (h.y - mu) * rstd * g.y + be.y;
    o.z = (h.z - mu) * rstd * g.z + be.z;
    o.w = (h.w - mu) * rstd * g.w + be.w;
    ((float4*)(out + (size_t)row * D_MOD))[tid] = o;
}

// ---------------- launch ----------------------------------------------------
extern "C" void kernel_launch(void* const* d_in, const int* in_sizes, int n_in,
                              void* d_out, int out_size)
{
    const float* x  = (const float*)d_in[0];
    const float* Wq = (const float*)d_in[1];
    const float* bq = (const float*)d_in[2];
    const float* Wk = (const float*)d_in[3];
    const float* bk = (const float*)d_in[4];
    const float* Wv = (const float*)d_in[5];
    const float* bv = (const float*)d_in[6];
    const float* Wo = (const float*)d_in[7];
    const float* bo = (const float*)d_in[8];
    const float* ga = (const float*)d_in[9];
    const float* be = (const float*)d_in[10];
    float* out = (float*)d_out;

    float *Qp, *Kp, *Vp, *Cp, *Pp;
    cudaGetSymbolAddress((void**)&Qp, g_Q);
    cudaGetSymbolAddress((void**)&Kp, g_K);
    cudaGetSymbolAddress((void**)&Vp, g_V);
    cudaGetSymbolAddress((void**)&Cp, g_ctx);
    cudaGetSymbolAddress((void**)&Pp, g_prj);

    dim3 gg(D_MOD / BN, ROWS / BM);              // (8, 32)
    sgemm_bias<true><<<gg, 256>>>(x, Wq, bq, Qp);
    sgemm_bias<true><<<gg, 256>>>(x, Wk, bk, Kp);
    sgemm_bias<true><<<gg, 256>>>(x, Wv, bv, Vp);

    attn_kernel<<<dim3(S_LEN / 128, B_SZ * H_NUM), 128>>>(Qp, Kp, Vp, Cp);

    sgemm_bias<false><<<gg, 256>>>(Cp, Wo, bo, Pp);

    ln_kernel<<<ROWS, 256>>>(x, Pp, ga, be, out);
}

// round 4
// speedup vs baseline: 3.8560x; 3.8560x over previous
#include <cuda_runtime.h>
#include <cstdint>
#include <math.h>

#define S_LEN 2048
#define D_MOD 1024
#define ROWS  4096          // B*S
#define NBH   32            // B*H

// ---------------- scratch (static; no allocations) ----------
__device__ __align__(128) float g_Q  [NBH * S_LEN * 64];
__device__ __align__(128) float g_K  [NBH * S_LEN * 64];
__device__ __align__(128) float g_V  [NBH * S_LEN * 64];
__device__ __align__(128) float g_Vt [NBH * 64 * S_LEN];    // [bh][dk][s]
__device__ __align__(128) float g_ctx[ROWS * D_MOD];
__device__ __align__(128) float g_prj[ROWS * D_MOD];
__device__ __align__(128) float g_xr [ROWS * D_MOD];
__device__ __align__(128) float g_WqkvT[3 * D_MOD * D_MOD]; // [3072][1024] K-major
__device__ __align__(128) float g_WoT  [D_MOD * D_MOD];

// ---------------- helpers ----------------
__device__ __forceinline__ uint32_t smem_u32(const void* p) {
    uint32_t a;
    asm("{ .reg .u64 t; cvta.to.shared.u64 t, %1; cvt.u32.u64 %0, t; }" : "=r"(a) : "l"(p));
    return a;
}
__device__ __forceinline__ float to_tf32r(float x) {
    uint32_t u;
    asm("cvt.rna.tf32.f32 %0, %1;" : "=r"(u) : "f"(x));
    return __uint_as_float(u);
}
__device__ __forceinline__ void cp16(uint32_t dst, const void* src) {
    asm volatile("cp.async.cg.shared.global [%0], [%1], 16;" :: "r"(dst), "l"(src) : "memory");
}
#define CP_COMMIT() asm volatile("cp.async.commit_group;" ::: "memory")
#define CP_WAIT0()  asm volatile("cp.async.wait_group 0;" ::: "memory")
#define CP_WAIT1()  asm volatile("cp.async.wait_group 1;" ::: "memory")

// D += A@B, m16n8k8 tf32 (A row-major, B col-major i.e. stored [n][k])
__device__ __forceinline__ void mma8(float* d, const uint32_t* a, const uint32_t* b) {
    asm volatile("mma.sync.aligned.m16n8k8.row.col.f32.tf32.tf32.f32 "
        "{%0,%1,%2,%3}, {%4,%5,%6,%7}, {%8,%9}, {%0,%1,%2,%3};"
        : "+f"(d[0]), "+f"(d[1]), "+f"(d[2]), "+f"(d[3])
        : "r"(a[0]), "r"(a[1]), "r"(a[2]), "r"(a[3]), "r"(b[0]), "r"(b[1]));
}

// ======================= tf32 mma.sync GEMM =======================
// C[4096, N] = A[4096,1024] @ W[N,1024]^T + bias.  BM=BN=128, BK=16.
// QKV=1: N=3072, scatter to [B,H,S,64] per matrix, tf32-rounded outputs.
#define GPAD 20

template <int QKV>
__global__ __launch_bounds__(256, 2) void gemm_mma(
    const float* __restrict__ A, const float* __restrict__ W,
    const float* __restrict__ b0, const float* __restrict__ b1, const float* __restrict__ b2,
    float* __restrict__ o0, float* __restrict__ o1, float* __restrict__ o2)
{
    __shared__ float As[2][128 * GPAD];
    __shared__ float Bs[2][128 * GPAD];

    const int tid = threadIdx.x;
    const int wid = tid >> 5, lane = tid & 31;
    const int g = lane >> 2, t = lane & 3;
    const int wm = wid & 1, wn = wid >> 1;       // warp 64 (M) x 32 (N)
    const int m0 = blockIdx.y * 128;
    const int n0 = blockIdx.x * 128;

    const uint32_t sA[2] = {smem_u32(As[0]), smem_u32(As[1])};
    const uint32_t sB[2] = {smem_u32(Bs[0]), smem_u32(Bs[1])};

    float acc[4][4][4];
#pragma unroll
    for (int i = 0; i < 4; i++)
#pragma unroll
        for (int j = 0; j < 4; j++)
#pragma unroll
            for (int r = 0; r < 4; r++) acc[i][j][r] = 0.f;

    // stage loader: 128 rows x 16 floats each for A and B
#define G_LOAD(st, kt) do {                                                       \
    _Pragma("unroll")                                                             \
    for (int i = 0; i < 2; i++) {                                                 \
        int j = tid + i * 256;                                                    \
        int r = j >> 2, c = (j & 3) * 4;                                          \
        cp16(sA[st] + (uint32_t)(r * GPAD + c) * 4,                               \
             A + (size_t)(m0 + r) * 1024 + (kt) * 16 + c);                        \
        cp16(sB[st] + (uint32_t)(r * GPAD + c) * 4,                               \
             W + (size_t)(n0 + r) * 1024 + (kt) * 16 + c);                        \
    }                                                                             \
    CP_COMMIT();                                                                  \
} while (0)

    G_LOAD(0, 0);
    for (int kt = 0; kt < 64; kt++) {
        const int st = kt & 1;
        if (kt < 63) { G_LOAD(st ^ 1, kt + 1); CP_WAIT1(); }
        else         { CP_WAIT0(); }
        __syncthreads();

        const float* Ab = As[st];
        const float* Bb = Bs[st];
#pragma unroll
        for (int ks = 0; ks < 2; ks++) {
            uint32_t af[4][4];
#pragma unroll
            for (int mt = 0; mt < 4; mt++) {
                const float* ap = Ab + (wm * 64 + mt * 16 + g) * GPAD + ks * 8 + t;
                af[mt][0] = __float_as_uint(ap[0]);
                af[mt][1] = __float_as_uint(ap[8 * GPAD]);
                af[mt][2] = __float_as_uint(ap[4]);
                af[mt][3] = __float_as_uint(ap[8 * GPAD + 4]);
            }
#pragma unroll
            for (int nt = 0; nt < 4; nt++) {
                const float* bp = Bb + (wn * 32 + nt * 8 + g) * GPAD + ks * 8 + t;
                uint32_t bf[2] = {__float_as_uint(bp[0]), __float_as_uint(bp[4])};
#pragma unroll
                for (int mt = 0; mt < 4; mt++) mma8(acc[mt][nt], af[mt], bf);
            }
        }
        __syncthreads();
    }

    // epilogue
#pragma unroll
    for (int mt = 0; mt < 4; mt++) {
        const int r0 = m0 + wm * 64 + mt * 16 + g;
#pragma unroll
        for (int nt = 0; nt < 4; nt++) {
            const int col = n0 + wn * 32 + nt * 8 + 2 * t;
            if (QKV) {
                const int mat = col >> 10, nl = col & 1023;
                const float* bias = (mat == 0 ? b0 : mat == 1 ? b1 : b2);
                float* op = (mat == 0 ? o0 : mat == 1 ? o1 : o2);
                const int h = nl >> 6, d = nl & 63;
                const float2 bv = *(const float2*)(bias + nl);
                const int b = r0 >> 11, s = r0 & 2047;
                float* p = op + ((size_t)((b * 16 + h) * 2048 + s)) * 64 + d;
                *(float2*)p = make_float2(to_tf32r(acc[mt][nt][0] + bv.x),
                                          to_tf32r(acc[mt][nt][1] + bv.y));
                *(float2*)(p + 8 * 64) = make_float2(to_tf32r(acc[mt][nt][2] + bv.x),
                                                     to_tf32r(acc[mt][nt][3] + bv.y));
            } else {
                const float2 bv = *(const float2*)(b0 + col);
                float* p = o0 + (size_t)r0 * 1024 + col;
                *(float2*)p = make_float2(acc[mt][nt][0] + bv.x, acc[mt][nt][1] + bv.y);
                *(float2*)(p + 8 * 1024) = make_float2(acc[mt][nt][2] + bv.x,
                                                       acc[mt][nt][3] + bv.y);
            }
        }
    }
}

// ======================= attention on mma.sync =======================
// CTA: 64 queries of one (b,h). 4 warps, each 16 q-rows. KV tiles of 64.
#define APAD 68
#define ATILE (64 * APAD)

__global__ __launch_bounds__(128) void attn_tc(
    const float* __restrict__ Q, const float* __restrict__ K,
    const float* __restrict__ Vt, float* __restrict__ Ctx)
{
    extern __shared__ float sm[];
    float* Qs = sm;                 // [64][68]
    float* Ps = sm + ATILE;         // [64][68]
    float* Ks = sm + 2 * ATILE;     // [2][64][68]
    float* Vs = sm + 4 * ATILE;     // [2][64][68]  (V^T: rows=dk, cols=key)

    const int bh = blockIdx.y;
    const int q0 = blockIdx.x * 64;
    const int tid = threadIdx.x;
    const int wid = tid >> 5, lane = tid & 31;
    const int g = lane >> 2, t = lane & 3;

    const float* Qb = Q  + (size_t)bh * S_LEN * 64;
    const float* Kb = K  + (size_t)bh * S_LEN * 64;
    const float* Vb = Vt + (size_t)bh * 64 * S_LEN;

    const uint32_t uQ = smem_u32(Qs);
    const uint32_t uK[2] = {smem_u32(Ks), smem_u32(Ks + ATILE)};
    const uint32_t uV[2] = {smem_u32(Vs), smem_u32(Vs + ATILE)};

#define LOAD_K(st, kt) do { _Pragma("unroll") for (int i = 0; i < 8; i++) { \
    int j = tid + i * 128; int r = j >> 4, c = (j & 15) * 4;                \
    cp16(uK[st] + (uint32_t)(r * APAD + c) * 4,                             \
         Kb + (size_t)((kt) * 64 + r) * 64 + c); } } while (0)
#define LOAD_V(st, kt) do { _Pragma("unroll") for (int i = 0; i < 8; i++) { \
    int j = tid + i * 128; int r = j >> 4, c = (j & 15) * 4;                \
    cp16(uV[st] + (uint32_t)(r * APAD + c) * 4,                             \
         Vb + (size_t)r * S_LEN + (kt) * 64 + c); } } while (0)

    // prologue: Q + K0 + V0 in one group
#pragma unroll
    for (int i = 0; i < 8; i++) {
        int j = tid + i * 128; int r = j >> 4, c = (j & 15) * 4;
        cp16(uQ + (uint32_t)(r * APAD + c) * 4, Qb + (size_t)(q0 + r) * 64 + c);
    }
    LOAD_K(0, 0); LOAD_V(0, 0); CP_COMMIT();

    float m0 = -1e30f, m1 = -1e30f, l0 = 0.f, l1 = 0.f;
    float oacc[8][4];
#pragma unroll
    for (int i = 0; i < 8; i++)
#pragma unroll
        for (int r = 0; r < 4; r++) oacc[i][r] = 0.f;

    const int rbase = wid * 16 + g;           // this thread's q-row (local)

    for (int kt = 0; kt < 32; kt++) {
        const int st = kt & 1;
        CP_WAIT0();
        __syncthreads();
        if (kt < 31) { LOAD_K(st ^ 1, kt + 1); LOAD_V(st ^ 1, kt + 1); CP_COMMIT(); }

        // ---- scores S = Q @ K^T over dk=64 ----
        float sacc[8][4];
#pragma unroll
        for (int i = 0; i < 8; i++)
#pragma unroll
            for (int r = 0; r < 4; r++) sacc[i][r] = 0.f;

        const float* Kt = Ks + st * ATILE;
#pragma unroll
        for (int ks = 0; ks < 8; ks++) {
            const float* ap = Qs + rbase * APAD + ks * 8 + t;
            uint32_t af[4] = {__float_as_uint(ap[0]), __float_as_uint(ap[8 * APAD]),
                              __float_as_uint(ap[4]), __float_as_uint(ap[8 * APAD + 4])};
#pragma unroll
            for (int nt = 0; nt < 8; nt++) {
                const float* bp = Kt + (nt * 8 + g) * APAD + ks * 8 + t;
                uint32_t bf[2] = {__float_as_uint(bp[0]), __float_as_uint(bp[4])};
                mma8(sacc[nt], af, bf);
            }
        }

        // ---- online softmax (rows rbase, rbase+8) ----
        float rmax0 = -1e30f, rmax1 = -1e30f;
#pragma unroll
        for (int nt = 0; nt < 8; nt++) {
#pragma unroll
            for (int r = 0; r < 4; r++) sacc[nt][r] *= 0.125f;
            rmax0 = fmaxf(rmax0, fmaxf(sacc[nt][0], sacc[nt][1]));
            rmax1 = fmaxf(rmax1, fmaxf(sacc[nt][2], sacc[nt][3]));
        }
        rmax0 = fmaxf(rmax0, __shfl_xor_sync(0xffffffffu, rmax0, 1));
        rmax0 = fmaxf(rmax0, __shfl_xor_sync(0xffffffffu, rmax0, 2));
        rmax1 = fmaxf(rmax1, __shfl_xor_sync(0xffffffffu, rmax1, 1));
        rmax1 = fmaxf(rmax1, __shfl_xor_sync(0xffffffffu, rmax1, 2));

        const float mn0 = fmaxf(m0, rmax0), mn1 = fmaxf(m1, rmax1);
        const float f0 = __expf(m0 - mn0), f1 = __expf(m1 - mn1);
        m0 = mn0; m1 = mn1;

        float rs0 = 0.f, rs1 = 0.f;
#pragma unroll
        for (int nt = 0; nt < 8; nt++) {
            const float p00 = to_tf32r(__expf(sacc[nt][0] - m0));
            const float p01 = to_tf32r(__expf(sacc[nt][1] - m0));
            const float p10 = to_tf32r(__expf(sacc[nt][2] - m1));
            const float p11 = to_tf32r(__expf(sacc[nt][3] - m1));
            rs0 += p00 + p01; rs1 += p10 + p11;
            *(float2*)&Ps[rbase * APAD + nt * 8 + 2 * t]       = make_float2(p00, p01);
            *(float2*)&Ps[(rbase + 8) * APAD + nt * 8 + 2 * t] = make_float2(p10, p11);
        }
        rs0 += __shfl_xor_sync(0xffffffffu, rs0, 1);
        rs0 += __shfl_xor_sync(0xffffffffu, rs0, 2);
        rs1 += __shfl_xor_sync(0xffffffffu, rs1, 1);
        rs1 += __shfl_xor_sync(0xffffffffu, rs1, 2);
        l0 = l0 * f0 + rs0; l1 = l1 * f1 + rs1;

#pragma unroll
        for (int nt = 0; nt < 8; nt++) {
            oacc[nt][0] *= f0; oacc[nt][1] *= f0;
            oacc[nt][2] *= f1; oacc[nt][3] *= f1;
        }
        __syncwarp();   // Ps rows are per-warp private: warp-level visibility suffices

        // ---- O += P @ V  (k = key index, n = dk, V^T layout [dk][key]) ----
        const float* Vtile = Vs + st * ATILE;
#pragma unroll
        for (int ks = 0; ks < 8; ks++) {
            const float* ap = Ps + rbase * APAD + ks * 8 + t;
            uint32_t af[4] = {__float_as_uint(ap[0]), __float_as_uint(ap[8 * APAD]),
                              __float_as_uint(ap[4]), __float_as_uint(ap[8 * APAD + 4])};
#pragma unroll
            for (int nt = 0; nt < 8; nt++) {
                const float* bp = Vtile + (nt * 8 + g) * APAD + ks * 8 + t;
                uint32_t bf[2] = {__float_as_uint(bp[0]), __float_as_uint(bp[4])};
                mma8(oacc[nt], af, bf);
            }
        }
        __syncwarp();
    }

    // ---- epilogue: ctx[b][s][h*64+d], tf32-rounded for the out-proj GEMM ----
    const float inv0 = 1.f / l0, inv1 = 1.f / l1;
    const int b = bh >> 4, h = bh & 15;
    const int row0 = q0 + rbase;
    float* base0 = Ctx + ((size_t)(b * 2048 + row0)) * 1024 + h * 64;
#pragma unroll
    for (int nt = 0; nt < 8; nt++) {
        const int col = nt * 8 + 2 * t;
        *(float2*)(base0 + col) = make_float2(to_tf32r(oacc[nt][0] * inv0),
                                              to_tf32r(oacc[nt][1] * inv0));
        *(float2*)(base0 + 8 * 1024 + col) = make_float2(to_tf32r(oacc[nt][2] * inv1),
                                                         to_tf32r(oacc[nt][3] * inv1));
    }
}

// ======================= prep kernels =======================
__global__ __launch_bounds__(256) void round_x_kernel(const float* __restrict__ x,
                                                      float* __restrict__ xr) {
    const int i = blockIdx.x * 256 + threadIdx.x;
    float4 v = ((const float4*)x)[i];
    v.x = to_tf32r(v.x); v.y = to_tf32r(v.y); v.z = to_tf32r(v.z); v.w = to_tf32r(v.w);
    ((float4*)xr)[i] = v;
}

__global__ __launch_bounds__(256) void prep_weights(
    const float* __restrict__ Wq, const float* __restrict__ Wk,
    const float* __restrict__ Wv, const float* __restrict__ Wo,
    float* __restrict__ WqkvT, float* __restrict__ WoT)
{
    __shared__ float tb[32][33];
    const int z = blockIdx.z;
    const float* src = (z == 0) ? Wq : (z == 1) ? Wk : (z == 2) ? Wv : Wo;
    float* dst = (z < 3) ? (WqkvT + (size_t)z * D_MOD * D_MOD) : WoT;
    const int k0 = blockIdx.x * 32, n0 = blockIdx.y * 32;
    const int tx = threadIdx.x, ty = threadIdx.y;   // 32 x 8
#pragma unroll
    for (int i = 0; i < 4; i++)
        tb[ty + i * 8][tx] = src[(size_t)(k0 + ty + i * 8) * D_MOD + n0 + tx];
    __syncthreads();
#pragma unroll
    for (int i = 0; i < 4; i++)
        dst[(size_t)(n0 + ty + i * 8) * D_MOD + k0 + tx] = to_tf32r(tb[tx][ty + i * 8]);
}

// V [bh][s][64] -> Vt [bh][64][s]
__global__ __launch_bounds__(256) void transpose_v(const float* __restrict__ V,
                                                   float* __restrict__ Vt) {
    __shared__ float tb[32][33];
    const int bh = blockIdx.z;
    const int s0 = blockIdx.x * 32, d0 = blockIdx.y * 32;
    const int tx = threadIdx.x, ty = threadIdx.y;   // 32 x 8
    const float* src = V + (size_t)bh * S_LEN * 64;
    float* dst = Vt + (size_t)bh * 64 * S_LEN;
#pragma unroll
    for (int i = 0; i < 4; i++)
        tb[ty + i * 8][tx] = src[(size_t)(s0 + ty + i * 8) * 64 + d0 + tx];
    __syncthreads();
#pragma unroll
    for (int i = 0; i < 4; i++)
        dst[(size_t)(d0 + ty + i * 8) * S_LEN + s0 + tx] = tb[tx][ty + i * 8];
}

// ---------------- residual + LayerNorm ------------------------------------
__global__ __launch_bounds__(256) void ln_kernel(
    const float* __restrict__ x, const float* __restrict__ prj,
    const float* __restrict__ gamma, const float* __restrict__ beta,
    float* __restrict__ out)
{
    const int row = blockIdx.x;
    const int tid = threadIdx.x;

    const float4 xv = ((const float4*)(x   + (size_t)row * D_MOD))[tid];
    const float4 pv = ((const float4*)(prj + (size_t)row * D_MOD))[tid];
    float4 h;
    h.x = xv.x + pv.x; h.y = xv.y + pv.y; h.z = xv.z + pv.z; h.w = xv.w + pv.w;

    float sum = h.x + h.y + h.z + h.w;
    float ssq = h.x * h.x + h.y * h.y + h.z * h.z + h.w * h.w;
#pragma unroll
    for (int o = 16; o > 0; o >>= 1) {
        sum += __shfl_xor_sync(0xffffffffu, sum, o);
        ssq += __shfl_xor_sync(0xffffffffu, ssq, o);
    }
    __shared__ float rs[8], rq[8];
    const int warp = tid >> 5, lane = tid & 31;
    if (lane == 0) { rs[warp] = sum; rq[warp] = ssq; }
    __syncthreads();
    float ts = 0.f, tq = 0.f;
#pragma unroll
    for (int i = 0; i < 8; i++) { ts += rs[i]; tq += rq[i]; }

    const float mu   = ts * (1.f / (float)D_MOD);
    const float var  = tq * (1.f / (float)D_MOD) - mu * mu;
    const float rstd = rsqrtf(var + 1e-5f);

    const float4 gg = ((const float4*)gamma)[tid];
    const float4 bb = ((const float4*)beta)[tid];
    float4 o;
    o.x = (h.x - mu) * rstd * gg.x + bb.x;
    o.y = (h.y - mu) * rstd * gg.y + bb.y;
    o.z = (h.z - mu) * rstd * gg.z + bb.z;
    o.w = (h.w - mu) * rstd * gg.w + bb.w;
    ((float4*)(out + (size_t)row * D_MOD))[tid] = o;
}

// ---------------- launch ----------------------------------------------------
extern "C" void kernel_launch(void* const* d_in, const int* in_sizes, int n_in,
                              void* d_out, int out_size)
{
    const float* x  = (const float*)d_in[0];
    const float* Wq = (const float*)d_in[1];
    const float* bq = (const float*)d_in[2];
    const float* Wk = (const float*)d_in[3];
    const float* bk = (const float*)d_in[4];
    const float* Wv = (const float*)d_in[5];
    const float* bv = (const float*)d_in[6];
    const float* Wo = (const float*)d_in[7];
    const float* bo = (const float*)d_in[8];
    const float* ga = (const float*)d_in[9];
    const float* be = (const float*)d_in[10];
    float* out = (float*)d_out;

    float *Qp, *Kp, *Vp, *Vtp, *Cp, *Pp, *Xr, *Wt, *WoT;
    cudaGetSymbolAddress((void**)&Qp,  g_Q);
    cudaGetSymbolAddress((void**)&Kp,  g_K);
    cudaGetSymbolAddress((void**)&Vp,  g_V);
    cudaGetSymbolAddress((void**)&Vtp, g_Vt);
    cudaGetSymbolAddress((void**)&Cp,  g_ctx);
    cudaGetSymbolAddress((void**)&Pp,  g_prj);
    cudaGetSymbolAddress((void**)&Xr,  g_xr);
    cudaGetSymbolAddress((void**)&Wt,  g_WqkvT);
    cudaGetSymbolAddress((void**)&WoT, g_WoT);

    const int attn_smem = 6 * ATILE * (int)sizeof(float);   // 104448
    cudaFuncSetAttribute(attn_tc, cudaFuncAttributeMaxDynamicSharedMemorySize, attn_smem);

    round_x_kernel<<<ROWS * D_MOD / 1024, 256>>>(x, Xr);
    prep_weights<<<dim3(32, 32, 4), dim3(32, 8)>>>(Wq, Wk, Wv, Wo, Wt, WoT);

    gemm_mma<1><<<dim3(24, 32), 256>>>(Xr, Wt, bq, bk, bv, Qp, Kp, Vp);

    transpose_v<<<dim3(64, 2, NBH), dim3(32, 8)>>>(Vp, Vtp);

    attn_tc<<<dim3(S_LEN / 64, NBH), 128, attn_smem>>>(Qp, Kp, Vtp, Cp);

    gemm_mma<0><<<dim3(8, 32), 256>>>(Cp, WoT, bo, bo, bo, Pp, Pp, Pp);

    ln_kernel<<<ROWS, 256>>>(x, Pp, ga, be, out);
}